// round 1
// baseline (speedup 1.0000x reference)
#include <cuda_runtime.h>

#define NB     64
#define NPER   2048
#define NTOT   131072          // NB*NPER
#define EE     1048576
#define KSEL   1639
#define PTOT   104896          // NB*KSEL
#define RANK_ASC 209715        // EE-1 - int(0.8*(EE-1))

// output layout (float32, concatenated in reference return order)
#define O1 6713344             // PTOT*64
#define O2 8810496             // O1 + 2*EE
#define O3 17199104            // O2 + EE*8
#define O4 17304000            // O3 + PTOT

__device__ int      g_perm[PTOT];
__device__ int      g_newidx[NTOT];
__device__ float    g_S[EE];
__device__ unsigned g_h1[65536];
__device__ unsigned g_h2[65536];
__device__ unsigned g_binT;
__device__ unsigned g_rank2;
__device__ unsigned g_uth;

__device__ __forceinline__ unsigned f2u(float f) {
    unsigned u = __float_as_uint(f);
    return (u & 0x80000000u) ? ~u : (u | 0x80000000u);
}

__global__ void k_zero() {
    int i = blockIdx.x * blockDim.x + threadIdx.x;
    if (i < 65536) { g_h1[i] = 0; g_h2[i] = 0; }
}

// Per-graph bitonic sort of (score desc, idx asc); writes perm, new_idx, batch_out.
__global__ void k_topk(const float* __restrict__ score, float* __restrict__ out) {
    __shared__ unsigned long long keys[NPER];
    int b = blockIdx.x, t = threadIdx.x;
    for (int i = t; i < NPER; i += blockDim.x) {
        unsigned su = f2u(score[b * NPER + i]);
        keys[i] = (((unsigned long long)(~su)) << 32) | (unsigned)i;
    }
    __syncthreads();
    for (int k = 2; k <= NPER; k <<= 1) {
        for (int j = k >> 1; j > 0; j >>= 1) {
            for (int i = t; i < NPER; i += blockDim.x) {
                int ixj = i ^ j;
                if (ixj > i) {
                    unsigned long long a = keys[i], c = keys[ixj];
                    bool up = ((i & k) == 0);
                    if ((a > c) == up) { keys[i] = c; keys[ixj] = a; }
                }
            }
            __syncthreads();
        }
    }
    for (int i = t; i < NPER; i += blockDim.x) {
        int local = (int)(keys[i] & 0xFFFFFFFFull);
        int node  = b * NPER + local;
        if (i < KSEL) {
            int p = b * KSEL + i;
            g_perm[p] = node;
            g_newidx[node] = p;
            out[O3 + p] = (float)b;   // batch_out (nodes are graph-sorted)
        } else {
            g_newidx[node] = -1;
        }
    }
}

// S[e] = exp(||x[row]-x[col]||). 16 threads per edge, float4 per thread:
// every row access is one contiguous 256B segment. Fuses pass-1 histogram.
__global__ void k_S(const int* __restrict__ ei, const float* __restrict__ x) {
    long long gid = (long long)blockIdx.x * blockDim.x + threadIdx.x;
    int  lane = threadIdx.x & 15;
    long long e = gid >> 4;
    if (e >= EE) return;
    int r = ei[e], c = ei[EE + e];
    const float4* xv = (const float4*)x;
    float4 a = xv[(long long)r * 16 + lane];
    float4 b = xv[(long long)c * 16 + lane];
    float dx = a.x - b.x, dy = a.y - b.y, dz = a.z - b.z, dw = a.w - b.w;
    float sq = dx * dx + dy * dy + dz * dz + dw * dw;
#pragma unroll
    for (int o = 8; o; o >>= 1) sq += __shfl_xor_sync(0xFFFFFFFFu, sq, o, 16);
    if (lane == 0) {
        float S = expf(sqrtf(sq));      // sq==0 -> S=1, matches _safe_norm forward
        g_S[e] = S;
        atomicAdd(&g_h1[f2u(S) >> 16], 1u);
    }
}

// One block: parallel scan of 65536-bin histogram, locate target rank's bin.
__global__ void k_scan(int pass) {
    __shared__ unsigned sh[1024];
    const unsigned* hist = pass ? g_h2 : g_h1;
    int t = threadIdx.x;
    int base = t * 64;
    unsigned s = 0;
    for (int i = 0; i < 64; i++) s += hist[base + i];
    sh[t] = s; __syncthreads();
    for (int off = 1; off < 1024; off <<= 1) {
        unsigned v = (t >= off) ? sh[t - off] : 0u;
        __syncthreads();
        sh[t] += v;
        __syncthreads();
    }
    unsigned excl = sh[t] - s;
    unsigned target = pass ? g_rank2 : (unsigned)RANK_ASC;
    if (target >= excl && target < excl + s) {
        unsigned cum = excl;
        for (int i = 0; i < 64; i++) {
            unsigned h = hist[base + i];
            if (target < cum + h) {
                if (pass == 0) { g_binT = (unsigned)(base + i); g_rank2 = target - cum; }
                else           { g_uth = (g_binT << 16) | (unsigned)(base + i); }
                break;
            }
            cum += h;
        }
    }
}

__global__ void k_hist2() {
    int e = blockIdx.x * blockDim.x + threadIdx.x;
    if (e >= EE) return;
    unsigned u = f2u(g_S[e]);
    if ((u >> 16) == g_binT) atomicAdd(&g_h2[u & 0xFFFFu], 1u);
}

// Per-edge outputs: remapped indices, masked attrs, select flag.
__global__ void k_edges(const int* __restrict__ ei, const float4* __restrict__ attr,
                        float* __restrict__ out) {
    int e = blockIdx.x * blockDim.x + threadIdx.x;
    if (e >= EE) return;
    int r = ei[e], c = ei[EE + e];
    int nr = g_newidx[r], nc = g_newidx[c];
    bool valid = (nr >= 0) && (nc >= 0);
    out[O1 + e]      = valid ? (float)nr : -1.0f;
    out[O1 + EE + e] = valid ? (float)nc : -1.0f;
    float4 a0 = attr[e * 2], a1 = attr[e * 2 + 1];
    if (!valid) { a0 = make_float4(0, 0, 0, 0); a1 = make_float4(0, 0, 0, 0); }
    float4* op = (float4*)(out + O2);
    op[e * 2] = a0; op[e * 2 + 1] = a1;
    out[O4 + e] = (f2u(g_S[e]) > g_uth) ? 1.0f : 0.0f;
}

// x_out gather: 16 threads (float4 each) per selected row.
__global__ void k_xout(const float4* __restrict__ xv, float4* __restrict__ outv) {
    int t = blockIdx.x * blockDim.x + threadIdx.x;
    if (t >= PTOT * 16) return;
    int p = t >> 4, j = t & 15;
    int node = g_perm[p];
    outv[p * 16 + j] = xv[node * 16 + j];
}

extern "C" void kernel_launch(void* const* d_in, const int* in_sizes, int n_in,
                              void* d_out, int out_size) {
    const float* x    = (const float*)d_in[0];
    const float* xs   = (const float*)d_in[1];
    const int*   ei   = (const int*)d_in[2];
    const float* attr = (const float*)d_in[3];
    float* out = (float*)d_out;

    k_zero<<<256, 256>>>();
    k_topk<<<NB, 1024>>>(xs, out);
    k_S<<<(EE * 16) / 256, 256>>>(ei, x);
    k_scan<<<1, 1024>>>(0);
    k_hist2<<<EE / 256, 256>>>();
    k_scan<<<1, 1024>>>(1);
    k_edges<<<EE / 256, 256>>>(ei, (const float4*)attr, out);
    k_xout<<<(PTOT * 16 + 255) / 256, 256>>>((const float4*)x, (float4*)out);
}

// round 4
// speedup vs baseline: 1.1741x; 1.1741x over previous
#include <cuda_runtime.h>

#define NB     64
#define NPER   2048
#define NTOT   131072          // NB*NPER
#define EE     1048576
#define KSEL   1639
#define PTOT   104896          // NB*KSEL
#define RANK_ASC 209715        // EE-1 - int(0.8*(EE-1))

// output layout (float32, concatenated in reference return order)
#define O1 6713344             // PTOT*64
#define O2 8810496             // O1 + 2*EE
#define O3 17199104            // O2 + EE*8
#define O4 17304000            // O3 + PTOT

__device__ int      g_perm[PTOT];
__device__ int      g_newidx[NTOT];
__device__ unsigned g_Su[EE];            // order-preserving uint key of S
__device__ unsigned g_h1[65536];
__device__ unsigned g_h2[65536];
__device__ unsigned g_binT;
__device__ unsigned g_rank2;
__device__ unsigned g_uth;

__device__ __forceinline__ unsigned f2u(float f) {
    unsigned u = __float_as_uint(f);
    return (u & 0x80000000u) ? ~u : (u | 0x80000000u);
}

__global__ void k_zero() {
    int i = blockIdx.x * blockDim.x + threadIdx.x;   // 16384 threads
    uint4 z = make_uint4(0, 0, 0, 0);
    ((uint4*)g_h1)[i] = z;
    ((uint4*)g_h2)[i] = z;
}

// Per-graph bitonic sort of (score desc, idx asc); writes perm, new_idx, batch_out.
__global__ void k_topk(const float* __restrict__ score, float* __restrict__ out) {
    __shared__ unsigned long long keys[NPER];
    int b = blockIdx.x, t = threadIdx.x;
    for (int i = t; i < NPER; i += blockDim.x) {
        unsigned su = f2u(score[b * NPER + i]);
        keys[i] = (((unsigned long long)(~su)) << 32) | (unsigned)i;
    }
    __syncthreads();
    for (int k = 2; k <= NPER; k <<= 1) {
        for (int j = k >> 1; j > 0; j >>= 1) {
            for (int i = t; i < NPER; i += blockDim.x) {
                int ixj = i ^ j;
                if (ixj > i) {
                    unsigned long long a = keys[i], c = keys[ixj];
                    bool up = ((i & k) == 0);
                    if ((a > c) == up) { keys[i] = c; keys[ixj] = a; }
                }
            }
            __syncthreads();
        }
    }
    for (int i = t; i < NPER; i += blockDim.x) {
        int local = (int)(keys[i] & 0xFFFFFFFFull);
        int node  = b * NPER + local;
        if (i < KSEL) {
            int p = b * KSEL + i;
            g_perm[p] = node;
            g_newidx[node] = p;
            out[O3 + p] = (float)b;   // batch_out (nodes are graph-sorted)
        } else {
            g_newidx[node] = -1;
        }
    }
}

// S[e] = exp(||x[row]-x[col]||), exact fp32. 16 threads/edge, float4 each:
// every row access = one contiguous 256B segment. Fuses pass-1 histogram.
__global__ void k_S(const int* __restrict__ ei, const float4* __restrict__ xv) {
    unsigned gid = blockIdx.x * blockDim.x + threadIdx.x;
    int lane = threadIdx.x & 15;
    unsigned e = gid >> 4;
    if (e >= EE) return;
    int r = ei[e], c = ei[EE + e];
    float4 a = __ldg(&xv[(size_t)r * 16 + lane]);
    float4 b = __ldg(&xv[(size_t)c * 16 + lane]);
    float dx = a.x - b.x, dy = a.y - b.y, dz = a.z - b.z, dw = a.w - b.w;
    float sq = dx * dx + dy * dy + dz * dz + dw * dw;
#pragma unroll
    for (int o = 8; o; o >>= 1) sq += __shfl_xor_sync(0xFFFFFFFFu, sq, o, 16);
    if (lane == 0) {
        float S = expf(sqrtf(sq));      // sq==0 -> S=1, matches _safe_norm forward
        unsigned u = f2u(S);
        g_Su[e] = u;
        atomicAdd(&g_h1[u >> 16], 1u);
    }
}

// One block, 1024 threads: each sums its 64-bin chunk with 16 independent
// uint4 loads (MLP=16), shuffle block-scan, winner re-reads its chunk (L1 hit).
__global__ void k_scan(int pass) {
    __shared__ unsigned warpsum[32];
    const unsigned* hist = pass ? g_h2 : g_h1;
    const uint4* hist4 = (const uint4*)hist;
    int t = threadIdx.x;
    unsigned s = 0;
#pragma unroll
    for (int i = 0; i < 16; i++) {
        uint4 v = hist4[t * 16 + i];
        s += v.x + v.y + v.z + v.w;
    }
    unsigned inc = s;
#pragma unroll
    for (int o = 1; o < 32; o <<= 1) {
        unsigned n = __shfl_up_sync(0xFFFFFFFFu, inc, o);
        if ((t & 31) >= o) inc += n;
    }
    if ((t & 31) == 31) warpsum[t >> 5] = inc;
    __syncthreads();
    if (t < 32) {
        unsigned w = warpsum[t];
#pragma unroll
        for (int o = 1; o < 32; o <<= 1) {
            unsigned n = __shfl_up_sync(0xFFFFFFFFu, w, o);
            if (t >= o) w += n;
        }
        warpsum[t] = w;
    }
    __syncthreads();
    unsigned incl = inc + ((t >= 32) ? warpsum[(t >> 5) - 1] : 0u);
    unsigned excl = incl - s;
    unsigned target = pass ? g_rank2 : (unsigned)RANK_ASC;
    if (target >= excl && target < incl) {
        unsigned cum = excl;
        for (int i = 0; i < 64; i++) {
            unsigned h = hist[t * 64 + i];
            if (target < cum + h) {
                if (pass == 0) { g_binT = (unsigned)(t * 64 + i); g_rank2 = target - cum; }
                else           { g_uth = (g_binT << 16) | (unsigned)(t * 64 + i); }
                break;
            }
            cum += h;
        }
    }
}

__global__ void k_hist2() {
    int e = blockIdx.x * blockDim.x + threadIdx.x;
    unsigned u = g_Su[e];
    if ((u >> 16) == g_binT) atomicAdd(&g_h2[u & 0xFFFFu], 1u);
}

// Per-edge outputs: remapped indices, masked attrs, select flag.
__global__ void k_edges(const int* __restrict__ ei, const float4* __restrict__ attr,
                        float* __restrict__ out) {
    int e = blockIdx.x * blockDim.x + threadIdx.x;
    int r = ei[e], c = ei[EE + e];
    int nr = g_newidx[r], nc = g_newidx[c];
    bool valid = (nr >= 0) && (nc >= 0);
    out[O1 + e]      = valid ? (float)nr : -1.0f;
    out[O1 + EE + e] = valid ? (float)nc : -1.0f;
    float4 a0 = attr[e * 2], a1 = attr[e * 2 + 1];
    if (!valid) { a0 = make_float4(0, 0, 0, 0); a1 = make_float4(0, 0, 0, 0); }
    float4* op = (float4*)(out + O2);
    op[e * 2] = a0; op[e * 2 + 1] = a1;
    out[O4 + e] = (g_Su[e] > g_uth) ? 1.0f : 0.0f;
}

// x_out gather: 16 threads (float4 each) per selected row (exact fp32).
__global__ void k_xout(const float4* __restrict__ xv, float4* __restrict__ outv) {
    int t = blockIdx.x * blockDim.x + threadIdx.x;
    if (t >= PTOT * 16) return;
    int p = t >> 4, j = t & 15;
    int node = g_perm[p];
    outv[p * 16 + j] = xv[node * 16 + j];
}

extern "C" void kernel_launch(void* const* d_in, const int* in_sizes, int n_in,
                              void* d_out, int out_size) {
    const float* x    = (const float*)d_in[0];
    const float* xs   = (const float*)d_in[1];
    const int*   ei   = (const int*)d_in[2];
    const float* attr = (const float*)d_in[3];
    float* out = (float*)d_out;

    k_zero<<<64, 256>>>();
    k_topk<<<NB, 1024>>>(xs, out);
    k_S<<<EE * 16 / 256, 256>>>(ei, (const float4*)x);
    k_scan<<<1, 1024>>>(0);
    k_hist2<<<EE / 256, 256>>>();
    k_scan<<<1, 1024>>>(1);
    k_edges<<<EE / 256, 256>>>(ei, (const float4*)attr, out);
    k_xout<<<(PTOT * 16 + 255) / 256, 256>>>((const float4*)x, (float4*)out);
}

// round 5
// speedup vs baseline: 1.2875x; 1.0966x over previous
#include <cuda_runtime.h>

#define NB     64
#define NPER   2048
#define NTOT   131072          // NB*NPER
#define EE     1048576
#define KSEL   1639
#define PTOT   104896          // NB*KSEL
#define RANK_ASC 209715        // EE-1 - int(0.8*(EE-1))

// output layout (float32, concatenated in reference return order)
#define O1 6713344             // PTOT*64
#define O2 8810496             // O1 + 2*EE
#define O3 17199104            // O2 + EE*8
#define O4 17304000            // O3 + PTOT

__device__ int      g_perm[PTOT];
__device__ int      g_newidx[NTOT];
__device__ unsigned g_Su[EE];            // order-preserving uint key of S
__device__ unsigned g_h1[65536];
__device__ unsigned g_h2[65536];
__device__ unsigned g_psum[64];
__device__ unsigned g_binT;
__device__ unsigned g_rank2;
__device__ unsigned g_uth;

__device__ __forceinline__ unsigned f2u(float f) {
    unsigned u = __float_as_uint(f);
    return (u & 0x80000000u) ? ~u : (u | 0x80000000u);
}

// Per-graph bitonic sort of (score desc, idx asc); writes perm, new_idx, batch_out.
// Fused: zero both histograms (runs before k_S's atomics by kernel ordering).
__global__ void k_topk(const float* __restrict__ score, float* __restrict__ out) {
    __shared__ unsigned long long keys[NPER];
    int b = blockIdx.x, t = threadIdx.x;
    int gt = b * 1024 + t;
    if (gt < 16384) {
        uint4 z = make_uint4(0, 0, 0, 0);
        ((uint4*)g_h1)[gt] = z;
        ((uint4*)g_h2)[gt] = z;
    }
    for (int i = t; i < NPER; i += blockDim.x) {
        unsigned su = f2u(score[b * NPER + i]);
        keys[i] = (((unsigned long long)(~su)) << 32) | (unsigned)i;
    }
    __syncthreads();
    for (int k = 2; k <= NPER; k <<= 1) {
        for (int j = k >> 1; j > 0; j >>= 1) {
            for (int i = t; i < NPER; i += blockDim.x) {
                int ixj = i ^ j;
                if (ixj > i) {
                    unsigned long long a = keys[i], c = keys[ixj];
                    bool up = ((i & k) == 0);
                    if ((a > c) == up) { keys[i] = c; keys[ixj] = a; }
                }
            }
            __syncthreads();
        }
    }
    for (int i = t; i < NPER; i += blockDim.x) {
        int local = (int)(keys[i] & 0xFFFFFFFFull);
        int node  = b * NPER + local;
        if (i < KSEL) {
            int p = b * KSEL + i;
            g_perm[p] = node;
            g_newidx[node] = p;
            out[O3 + p] = (float)b;   // batch_out (nodes are graph-sorted)
        } else {
            g_newidx[node] = -1;
        }
    }
}

// Fused edge kernel: S[e]=exp(||x[row]-x[col]||) exact fp32 (16 threads/edge,
// one contiguous 256B segment per row read) + pass-1 histogram + remapped
// edge indices + masked attr copy. Overlaps L2-bound gather with DRAM streams.
__global__ void k_S(const int* __restrict__ ei, const float4* __restrict__ xv,
                    const float4* __restrict__ attr4, float* __restrict__ out) {
    unsigned gid = blockIdx.x * blockDim.x + threadIdx.x;
    int lane = threadIdx.x & 15;
    unsigned e = gid >> 4;
    if (e >= EE) return;
    int r = ei[e], c = ei[EE + e];
    float4 a = __ldg(&xv[(size_t)r * 16 + lane]);
    float4 b = __ldg(&xv[(size_t)c * 16 + lane]);
    float dx = a.x - b.x, dy = a.y - b.y, dz = a.z - b.z, dw = a.w - b.w;
    float sq = dx * dx + dy * dy + dz * dz + dw * dw;
#pragma unroll
    for (int o = 8; o; o >>= 1) sq += __shfl_xor_sync(0xFFFFFFFFu, sq, o, 16);
    if (lane < 2) {
        int nr = g_newidx[r], nc = g_newidx[c];
        bool valid = (nr >= 0) && (nc >= 0);
        if (lane == 0) {
            float S = expf(sqrtf(sq));   // sq==0 -> S=1, matches _safe_norm forward
            unsigned u = f2u(S);
            g_Su[e] = u;
            atomicAdd(&g_h1[u >> 16], 1u);
            out[O1 + e]      = valid ? (float)nr : -1.0f;
        } else {
            out[O1 + EE + e] = valid ? (float)nc : -1.0f;
        }
        float4 av = valid ? attr4[e * 2 + lane] : make_float4(0, 0, 0, 0);
        ((float4*)(out + O2))[e * 2 + lane] = av;
    }
}

// Parallel partial sums: 64 blocks x 256 threads, each thread 4 bins (uint4).
__global__ void k_sum(int pass) {
    const uint4* hist4 = (const uint4*)(pass ? g_h2 : g_h1);
    __shared__ unsigned sh[8];
    int t = threadIdx.x;
    uint4 v = hist4[blockIdx.x * 256 + t];
    unsigned s = v.x + v.y + v.z + v.w;
#pragma unroll
    for (int o = 16; o; o >>= 1) s += __shfl_xor_sync(0xFFFFFFFFu, s, o);
    if ((t & 31) == 0) sh[t >> 5] = s;
    __syncthreads();
    if (t < 8) {
        s = sh[t];
#pragma unroll
        for (int o = 4; o; o >>= 1) s += __shfl_xor_sync(0xFFu, s, o, 8);
        if (t == 0) g_psum[blockIdx.x] = s;
    }
}

// One block: locate target chunk from 64 partials, then 1024 threads scan
// the winning 1024-bin chunk (1 bin per thread, shuffle block-scan).
__global__ void k_find(int pass) {
    __shared__ unsigned warpsum[32];
    __shared__ unsigned s_excl;
    __shared__ int s_blk;
    const unsigned* hist = pass ? g_h2 : g_h1;
    int t = threadIdx.x;
    unsigned target = pass ? g_rank2 : (unsigned)RANK_ASC;
    if (t == 0) {
        unsigned cum = 0;
        int B = 0;
        for (int i = 0; i < 64; i++) {
            unsigned p = g_psum[i];
            if (target < cum + p) { B = i; break; }
            cum += p;
        }
        s_excl = cum; s_blk = B;
    }
    __syncthreads();
    int B = s_blk;
    unsigned h = hist[B * 1024 + t];
    unsigned inc = h;
#pragma unroll
    for (int o = 1; o < 32; o <<= 1) {
        unsigned n = __shfl_up_sync(0xFFFFFFFFu, inc, o);
        if ((t & 31) >= o) inc += n;
    }
    if ((t & 31) == 31) warpsum[t >> 5] = inc;
    __syncthreads();
    if (t < 32) {
        unsigned w = warpsum[t];
#pragma unroll
        for (int o = 1; o < 32; o <<= 1) {
            unsigned n = __shfl_up_sync(0xFFFFFFFFu, w, o);
            if (t >= o) w += n;
        }
        warpsum[t] = w;
    }
    __syncthreads();
    unsigned incl = inc + ((t >= 32) ? warpsum[(t >> 5) - 1] : 0u);
    unsigned excl = s_excl + incl - h;
    if (target >= excl && target < excl + h) {
        unsigned bin = (unsigned)(B * 1024 + t);
        if (pass == 0) { g_binT = bin; g_rank2 = target - excl; }
        else           { g_uth = (g_binT << 16) | bin; }
    }
}

__global__ void k_hist2() {
    int e = blockIdx.x * blockDim.x + threadIdx.x;
    unsigned u = g_Su[e];
    if ((u >> 16) == g_binT) atomicAdd(&g_h2[u & 0xFFFFu], 1u);
}

// Final fused kernel: x_out gather (16 threads/row, exact fp32) + select flags.
__global__ void k_final(const float4* __restrict__ xv, float* __restrict__ out) {
    int t = blockIdx.x * blockDim.x + threadIdx.x;
    if (t < EE) out[O4 + t] = (g_Su[t] > g_uth) ? 1.0f : 0.0f;
    if (t < PTOT * 16) {
        int p = t >> 4, j = t & 15;
        int node = g_perm[p];
        ((float4*)out)[p * 16 + j] = xv[(size_t)node * 16 + j];
    }
}

extern "C" void kernel_launch(void* const* d_in, const int* in_sizes, int n_in,
                              void* d_out, int out_size) {
    const float* x    = (const float*)d_in[0];
    const float* xs   = (const float*)d_in[1];
    const int*   ei   = (const int*)d_in[2];
    const float* attr = (const float*)d_in[3];
    float* out = (float*)d_out;

    k_topk<<<NB, 1024>>>(xs, out);
    k_S<<<EE * 16 / 256, 256>>>(ei, (const float4*)x, (const float4*)attr, out);
    k_sum<<<64, 256>>>(0);
    k_find<<<1, 1024>>>(0);
    k_hist2<<<EE / 256, 256>>>();
    k_sum<<<64, 256>>>(1);
    k_find<<<1, 1024>>>(1);
    k_final<<<PTOT * 16 / 256, 256>>>((const float4*)x, out);
}

// round 6
// speedup vs baseline: 1.3106x; 1.0179x over previous
#include <cuda_runtime.h>

#define NB     64
#define NPER   2048
#define NTOT   131072          // NB*NPER
#define EE     1048576
#define KSEL   1639
#define PTOT   104896          // NB*KSEL
#define RANK_ASC 209715        // EE-1 - int(0.8*(EE-1))

// output layout (float32, concatenated in reference return order)
#define O1 6713344             // PTOT*64
#define O2 8810496             // O1 + 2*EE
#define O3 17199104            // O2 + EE*8
#define O4 17304000            // O3 + PTOT

__device__ int      g_perm[PTOT];
__device__ int      g_newidx[NTOT];
__device__ unsigned g_Su[EE];            // order-preserving uint key of S
__device__ unsigned g_h1[65536];
__device__ unsigned g_h2[65536];
__device__ unsigned g_psum[64];
__device__ unsigned g_binT;
__device__ unsigned g_rank2;
__device__ unsigned g_uth;

__device__ __forceinline__ unsigned f2u(float f) {
    unsigned u = __float_as_uint(f);
    return (u & 0x80000000u) ? ~u : (u | 0x80000000u);
}

// Zero hist1 + write batch_out (independent of topk: batch_out[p] = p/KSEL).
__global__ void k_zeroA(float* __restrict__ out) {
    int t = blockIdx.x * blockDim.x + threadIdx.x;
    if (t < 16384) ((uint4*)g_h1)[t] = make_uint4(0, 0, 0, 0);
    if (t < PTOT) out[O3 + t] = (float)(t / KSEL);
}

__global__ void k_zeroB() {
    int t = blockIdx.x * blockDim.x + threadIdx.x;
    ((uint4*)g_h2)[t] = make_uint4(0, 0, 0, 0);
}

// Per-graph bitonic sort of (score desc, idx asc); writes perm + new_idx.
__global__ void k_topk(const float* __restrict__ score) {
    __shared__ unsigned long long keys[NPER];
    int b = blockIdx.x, t = threadIdx.x;
    for (int i = t; i < NPER; i += blockDim.x) {
        unsigned su = f2u(score[b * NPER + i]);
        keys[i] = (((unsigned long long)(~su)) << 32) | (unsigned)i;
    }
    __syncthreads();
    for (int k = 2; k <= NPER; k <<= 1) {
        for (int j = k >> 1; j > 0; j >>= 1) {
            for (int i = t; i < NPER; i += blockDim.x) {
                int ixj = i ^ j;
                if (ixj > i) {
                    unsigned long long a = keys[i], c = keys[ixj];
                    bool up = ((i & k) == 0);
                    if ((a > c) == up) { keys[i] = c; keys[ixj] = a; }
                }
            }
            __syncthreads();
        }
    }
    for (int i = t; i < NPER; i += blockDim.x) {
        int local = (int)(keys[i] & 0xFFFFFFFFull);
        int node  = b * NPER + local;
        if (i < KSEL) {
            int p = b * KSEL + i;
            g_perm[p] = node;
            g_newidx[node] = p;
        } else {
            g_newidx[node] = -1;
        }
    }
}

// Fused edge kernel, 2 edges per 16-lane group (MLP=4 row-loads in flight):
// S=exp(||x[row]-x[col]||) exact fp32 + pass-1 histogram + remapped edge
// indices + masked attr copy.
__global__ void k_S(const int* __restrict__ ei, const float4* __restrict__ xv,
                    const float4* __restrict__ attr4, float* __restrict__ out) {
    unsigned gid = blockIdx.x * blockDim.x + threadIdx.x;   // EE*8 threads
    int lane = threadIdx.x & 15;
    unsigned p = gid >> 4;                                   // pair id
    unsigned e0 = 2 * p, e1 = 2 * p + 1;
    int r0 = ei[e0], c0 = ei[EE + e0];
    int r1 = ei[e1], c1 = ei[EE + e1];
    float4 a0 = __ldg(&xv[(size_t)r0 * 16 + lane]);
    float4 b0 = __ldg(&xv[(size_t)c0 * 16 + lane]);
    float4 a1 = __ldg(&xv[(size_t)r1 * 16 + lane]);
    float4 b1 = __ldg(&xv[(size_t)c1 * 16 + lane]);
    float dx = a0.x - b0.x, dy = a0.y - b0.y, dz = a0.z - b0.z, dw = a0.w - b0.w;
    float sq0 = dx * dx + dy * dy + dz * dz + dw * dw;
    dx = a1.x - b1.x; dy = a1.y - b1.y; dz = a1.z - b1.z; dw = a1.w - b1.w;
    float sq1 = dx * dx + dy * dy + dz * dz + dw * dw;
#pragma unroll
    for (int o = 8; o; o >>= 1) {
        sq0 += __shfl_xor_sync(0xFFFFFFFFu, sq0, o, 16);
        sq1 += __shfl_xor_sync(0xFFFFFFFFu, sq1, o, 16);
    }
    if (lane < 4) {
        // lanes 0,1 -> edge e0;  lanes 2,3 -> edge e1
        unsigned e = (lane < 2) ? e0 : e1;
        int r = (lane < 2) ? r0 : r1;
        int c = (lane < 2) ? c0 : c1;
        float sq = (lane < 2) ? sq0 : sq1;
        int nr = g_newidx[r], nc = g_newidx[c];
        bool valid = (nr >= 0) && (nc >= 0);
        if ((lane & 1) == 0) {
            float S = expf(sqrtf(sq));   // sq==0 -> S=1, matches _safe_norm forward
            unsigned u = f2u(S);
            g_Su[e] = u;
            atomicAdd(&g_h1[u >> 16], 1u);
            out[O1 + e]      = valid ? (float)nr : -1.0f;
        } else {
            out[O1 + EE + e] = valid ? (float)nc : -1.0f;
        }
        float4 av = valid ? attr4[e * 2 + (lane & 1)] : make_float4(0, 0, 0, 0);
        ((float4*)(out + O2))[e * 2 + (lane & 1)] = av;
    }
}

// Parallel partial sums: 64 blocks x 256 threads, each thread 4 bins (uint4).
__global__ void k_sum(int pass) {
    const uint4* hist4 = (const uint4*)(pass ? g_h2 : g_h1);
    __shared__ unsigned sh[8];
    int t = threadIdx.x;
    uint4 v = hist4[blockIdx.x * 256 + t];
    unsigned s = v.x + v.y + v.z + v.w;
#pragma unroll
    for (int o = 16; o; o >>= 1) s += __shfl_xor_sync(0xFFFFFFFFu, s, o);
    if ((t & 31) == 0) sh[t >> 5] = s;
    __syncthreads();
    if (t < 8) {
        s = sh[t];
#pragma unroll
        for (int o = 4; o; o >>= 1) s += __shfl_xor_sync(0xFFu, s, o, 8);
        if (t == 0) g_psum[blockIdx.x] = s;
    }
}

// One block: psums staged via SMEM (kills the dependent-global-load chain),
// then 1024 threads shuffle-scan the winning 1024-bin chunk.
__global__ void k_find(int pass) {
    __shared__ unsigned warpsum[32];
    __shared__ unsigned spsum[64];
    __shared__ unsigned s_excl;
    __shared__ int s_blk;
    const unsigned* hist = pass ? g_h2 : g_h1;
    int t = threadIdx.x;
    unsigned target = pass ? g_rank2 : (unsigned)RANK_ASC;
    if (t < 64) spsum[t] = g_psum[t];
    __syncthreads();
    if (t == 0) {
        unsigned cum = 0;
        int B = 0;
        for (int i = 0; i < 64; i++) {
            unsigned p = spsum[i];
            if (target < cum + p) { B = i; break; }
            cum += p;
        }
        s_excl = cum; s_blk = B;
    }
    __syncthreads();
    int B = s_blk;
    unsigned h = hist[B * 1024 + t];
    unsigned inc = h;
#pragma unroll
    for (int o = 1; o < 32; o <<= 1) {
        unsigned n = __shfl_up_sync(0xFFFFFFFFu, inc, o);
        if ((t & 31) >= o) inc += n;
    }
    if ((t & 31) == 31) warpsum[t >> 5] = inc;
    __syncthreads();
    if (t < 32) {
        unsigned w = warpsum[t];
#pragma unroll
        for (int o = 1; o < 32; o <<= 1) {
            unsigned n = __shfl_up_sync(0xFFFFFFFFu, w, o);
            if (t >= o) w += n;
        }
        warpsum[t] = w;
    }
    __syncthreads();
    unsigned incl = inc + ((t >= 32) ? warpsum[(t >> 5) - 1] : 0u);
    unsigned excl = s_excl + incl - h;
    if (target >= excl && target < excl + h) {
        unsigned bin = (unsigned)(B * 1024 + t);
        if (pass == 0) { g_binT = bin; g_rank2 = target - excl; }
        else           { g_uth = (g_binT << 16) | bin; }
    }
}

__global__ void k_hist2() {
    int e = blockIdx.x * blockDim.x + threadIdx.x;
    unsigned u = g_Su[e];
    if ((u >> 16) == g_binT) atomicAdd(&g_h2[u & 0xFFFFu], 1u);
}

// Final fused kernel: x_out gather (16 threads/row, exact fp32) + select flags.
__global__ void k_final(const float4* __restrict__ xv, float* __restrict__ out) {
    int t = blockIdx.x * blockDim.x + threadIdx.x;
    if (t < EE) out[O4 + t] = (g_Su[t] > g_uth) ? 1.0f : 0.0f;
    if (t < PTOT * 16) {
        int p = t >> 4, j = t & 15;
        int node = g_perm[p];
        ((float4*)out)[p * 16 + j] = xv[(size_t)node * 16 + j];
    }
}

extern "C" void kernel_launch(void* const* d_in, const int* in_sizes, int n_in,
                              void* d_out, int out_size) {
    const float* x    = (const float*)d_in[0];
    const float* xs   = (const float*)d_in[1];
    const int*   ei   = (const int*)d_in[2];
    const float* attr = (const float*)d_in[3];
    float* out = (float*)d_out;

    k_zeroA<<<(PTOT + 255) / 256, 256>>>(out);     // #1
    k_zeroB<<<64, 256>>>();                        // #2
    k_topk<<<NB, 1024>>>(xs);                      // #3
    k_S<<<EE * 8 / 256, 256>>>(ei, (const float4*)x,
                               (const float4*)attr, out);   // #4 (ncu capture slot)
    k_sum<<<64, 256>>>(0);                         // #5
    k_find<<<1, 1024>>>(0);                        // #6
    k_hist2<<<EE / 256, 256>>>();                  // #7
    k_sum<<<64, 256>>>(1);                         // #8
    k_find<<<1, 1024>>>(1);                        // #9
    k_final<<<PTOT * 16 / 256, 256>>>((const float4*)x, out);  // #10
}